// round 1
// baseline (speedup 1.0000x reference)
#include <cuda_runtime.h>
#include <math.h>

// ---------------------------------------------------------------------------
// Problem constants
// ---------------------------------------------------------------------------
#define B_SZ    64
#define L_SZ    512
#define D_EMB   768
#define D_HID   17
#define D_OBS   17
#define N_SRC   24
#define NM1     16          // D_OBS - 1
#define TRANS_COLS (D_HID * D_HID)   // 289
#define M_ROWS  (B_SZ * L_SZ)        // 32768

// output layout (flattened concat of the 5 reference outputs, in order)
#define OFF_TRANS 0ULL
#define SZ_TRANS  ((size_t)M_ROWS * TRANS_COLS)                 // 9,469,952
#define OFF_EMISS (OFF_TRANS + SZ_TRANS)
#define SZ_EMISS  ((size_t)B_SZ * N_SRC * TRANS_COLS)           // 443,904
#define OFF_O2O   (OFF_EMISS + SZ_EMISS)
#define SZ_O2O    ((size_t)B_SZ * N_SRC)                        // 1,536
#define OFF_L2L   (OFF_O2O + SZ_O2O)
#define SZ_L2L    ((size_t)B_SZ * N_SRC * NM1)                  // 24,576
#define OFF_WXOR  (OFF_L2L + SZ_L2L)
#define SZ_WXOR   ((size_t)B_SZ * N_SRC * NM1 * NM1)            // 393,216

// scratch (device globals; no allocations allowed)
__device__ float g_o2o[B_SZ * N_SRC];
__device__ float g_e2e[B_SZ * N_SRC * NM1];
__device__ float g_exp[B_SZ * N_SRC * NM1];

// ---------------------------------------------------------------------------
// Kernel 1: trans logits GEMM   C[M,289] = embs[M,768] . W_trans[289,768]^T + b
// BM=128 BN=64 BK=16, 256 threads, 8x4 micro-tile
// ---------------------------------------------------------------------------
#define BM 128
#define BN 64
#define BK 16
#define TM 8
#define TN 4

__global__ __launch_bounds__(256) void gemm_trans_kernel(
    const float* __restrict__ A,      // [M, 768]
    const float* __restrict__ W,      // [289, 768]
    const float* __restrict__ bias,   // [289]
    float* __restrict__ C)            // [M, 289]
{
    __shared__ float As[BK][BM];      // transposed stage
    __shared__ float Ws[BK][BN];

    const int bm = blockIdx.y * BM;
    const int bn = blockIdx.x * BN;
    const int tid = threadIdx.x;
    const int tx = tid & 15;          // 16 column-groups
    const int ty = tid >> 4;          // 16 row-groups

    float acc[TM][TN];
#pragma unroll
    for (int i = 0; i < TM; i++)
#pragma unroll
        for (int j = 0; j < TN; j++) acc[i][j] = 0.f;

    for (int k0 = 0; k0 < D_EMB; k0 += BK) {
        // load A tile: 128 rows x 16 k -> 512 float4 slots, 2 per thread
#pragma unroll
        for (int l = 0; l < 2; l++) {
            int slot = tid + l * 256;
            int row  = slot >> 2;            // 0..127
            int c4   = (slot & 3) << 2;      // 0,4,8,12
            const float4 v = *(const float4*)(A + (size_t)(bm + row) * D_EMB + k0 + c4);
            As[c4 + 0][row] = v.x;
            As[c4 + 1][row] = v.y;
            As[c4 + 2][row] = v.z;
            As[c4 + 3][row] = v.w;
        }
        // load W tile: 64 rows x 16 k -> 256 float4 slots, 1 per thread
        {
            int row = tid >> 2;              // 0..63
            int c4  = (tid & 3) << 2;
            int n   = bn + row;
            float4 v = make_float4(0.f, 0.f, 0.f, 0.f);
            if (n < TRANS_COLS)
                v = *(const float4*)(W + (size_t)n * D_EMB + k0 + c4);
            Ws[c4 + 0][row] = v.x;
            Ws[c4 + 1][row] = v.y;
            Ws[c4 + 2][row] = v.z;
            Ws[c4 + 3][row] = v.w;
        }
        __syncthreads();

#pragma unroll
        for (int kk = 0; kk < BK; kk++) {
            float a[TM], w[TN];
            *(float4*)&a[0] = *(const float4*)&As[kk][ty * TM];
            *(float4*)&a[4] = *(const float4*)&As[kk][ty * TM + 4];
            *(float4*)&w[0] = *(const float4*)&Ws[kk][tx * TN];
#pragma unroll
            for (int i = 0; i < TM; i++)
#pragma unroll
                for (int j = 0; j < TN; j++)
                    acc[i][j] = fmaf(a[i], w[j], acc[i][j]);
        }
        __syncthreads();
    }

    // epilogue: add bias, store (softmax done by second pass)
#pragma unroll
    for (int i = 0; i < TM; i++) {
        int m = bm + ty * TM + i;
#pragma unroll
        for (int j = 0; j < TN; j++) {
            int n = bn + tx * TN + j;
            if (n < TRANS_COLS)
                C[(size_t)m * TRANS_COLS + n] = acc[i][j] + bias[n];
        }
    }
}

// ---------------------------------------------------------------------------
// Kernel 2: in-place softmax over contiguous groups of 17
// 256 groups per block, shared-staged. 17-stride -> bank-conflict free.
// ---------------------------------------------------------------------------
__global__ __launch_bounds__(256) void softmax17_kernel(float* __restrict__ out)
{
    __shared__ float buf[256 * D_HID];
    const size_t base = (size_t)blockIdx.x * (256 * D_HID);

    for (int i = threadIdx.x; i < 256 * D_HID; i += 256)
        buf[i] = out[base + i];
    __syncthreads();

    float* v = buf + threadIdx.x * D_HID;
    float mx = v[0];
#pragma unroll
    for (int i = 1; i < D_HID; i++) mx = fmaxf(mx, v[i]);
    float s = 0.f;
#pragma unroll
    for (int i = 0; i < D_HID; i++) {
        float e = __expf(v[i] - mx);
        v[i] = e;
        s += e;
    }
    float inv = 1.f / s;
#pragma unroll
    for (int i = 0; i < D_HID; i++) v[i] *= inv;
    __syncthreads();

    for (int i = threadIdx.x; i < 256 * D_HID; i += 256)
        out[base + i] = buf[i];
}

// ---------------------------------------------------------------------------
// Kernel 3: tiny GEMVs off x0 = embs[b,0,:]   (792 columns, warp-reduced)
// grid = 64 blocks (one per b), 256 threads = 8 warps
// cols 0..23 -> W_2o, 24..407 -> W_2e, 408..791 -> W_exp
// ---------------------------------------------------------------------------
__global__ __launch_bounds__(256) void small_gemv_kernel(
    const float* __restrict__ embs,
    const float* __restrict__ W2o, const float* __restrict__ b2o,
    const float* __restrict__ W2e, const float* __restrict__ b2e,
    const float* __restrict__ Wexp, const float* __restrict__ bexp)
{
    __shared__ float x0[D_EMB];
    const int b = blockIdx.x;
    const float* xrow = embs + (size_t)b * L_SZ * D_EMB;   // embs[b, 0, :]
    for (int i = threadIdx.x; i < D_EMB; i += 256) x0[i] = xrow[i];
    __syncthreads();

    const int warp = threadIdx.x >> 5;
    const int lane = threadIdx.x & 31;

    for (int col = warp; col < 24 + 2 * N_SRC * NM1; col += 8) {
        const float* w;
        float bias;
        float* dst;
        if (col < 24) {
            w = W2o + (size_t)col * D_EMB;  bias = b2o[col];
            dst = &g_o2o[b * N_SRC + col];
        } else if (col < 24 + N_SRC * NM1) {
            int c = col - 24;
            w = W2e + (size_t)c * D_EMB;    bias = b2e[c];
            dst = &g_e2e[b * N_SRC * NM1 + c];
        } else {
            int c = col - 24 - N_SRC * NM1;
            w = Wexp + (size_t)c * D_EMB;   bias = bexp[c];
            dst = &g_exp[b * N_SRC * NM1 + c];
        }
        float s = 0.f;
        for (int k = lane; k < D_EMB; k += 32) s = fmaf(x0[k], w[k], s);
#pragma unroll
        for (int o = 16; o > 0; o >>= 1) s += __shfl_xor_sync(0xffffffffu, s, o);
        if (lane == 0) *dst = s + bias;
    }
}

// ---------------------------------------------------------------------------
// Kernel 4: finalize — softmax over sources, prob_scaling, emissions, wxor.
// grid = 64 blocks (one per b), 256 threads.
// ---------------------------------------------------------------------------
__device__ __forceinline__ float sigmoidf_(float x) {
    return 1.f / (1.f + __expf(-x));
}

__global__ __launch_bounds__(256) void finalize_kernel(
    const float* __restrict__ lut,   // [24,16,16]
    float* __restrict__ out)
{
    __shared__ float l2l[N_SRC * NM1];     // conc_l2l (after prob_scaling)
    __shared__ float wsc[N_SRC * NM1];     // sigmoid(exp logits)
    __shared__ float o2o[N_SRC];

    const int b = blockIdx.x;
    const int tid = threadIdx.x;

    for (int t = tid; t < N_SRC * NM1; t += 256) {
        l2l[t] = g_e2e[b * N_SRC * NM1 + t];
        wsc[t] = sigmoidf_(g_exp[b * N_SRC * NM1 + t]);
    }
    if (tid < N_SRC) o2o[tid] = sigmoidf_(g_o2o[b * N_SRC + tid]);
    __syncthreads();

    // softmax over the 24 sources (axis=-2), per column j, then prob_scaling
    if (tid < NM1) {
        const int j = tid;
        float mx = -1e30f;
        for (int s = 0; s < N_SRC; s++) mx = fmaxf(mx, l2l[s * NM1 + j]);
        float sum = 0.f;
        for (int s = 0; s < N_SRC; s++) sum += __expf(l2l[s * NM1 + j] - mx);
        const float inv = 1.f / sum;
        // prob_scaling: r = 1/24, e1=1, e2=4, bcoef = (1-r)^-3
        const float r = 1.f / 24.f;
        const float omr = 1.f - r;
        const float bco = 1.f / (omr * omr * omr);
        for (int s = 0; s < N_SRC; s++) {
            float xn = __expf(l2l[s * NM1 + j] - mx) * inv;
            float om = 1.f - xn;
            float om2 = om * om;
            float scaled = (xn < r) ? xn : (1.f - bco * om2 * om2);
            l2l[s * NM1 + j] = scaled;
        }
    }
    __syncthreads();

    // write conc_o2o and conc_l2l outputs
    if (tid < N_SRC) out[OFF_O2O + (size_t)b * N_SRC + tid] = o2o[tid];
    for (int t = tid; t < N_SRC * NM1; t += 256)
        out[OFF_L2L + (size_t)b * N_SRC * NM1 + t] = l2l[t];

    // scaled_wxor[b,s,i,j] = wsc[s,j] * lut[s,j,i]
    for (int p = tid; p < N_SRC * NM1; p += 256) {
        const int s = p >> 4;
        const int i = p & 15;
        float* dst = out + OFF_WXOR + (size_t)b * (N_SRC * NM1 * NM1) + (size_t)p * NM1;
#pragma unroll
        for (int j = 0; j < NM1; j++)
            dst[j] = wsc[s * NM1 + j] * lut[s * 256 + j * NM1 + i];
    }

    // emission probs: 24 sources x 17 rows, each row 17 values -> normalize
    const float tp = 1.f / (float)D_OBS;   // split_point = 1/17
    for (int p = tid; p < N_SRC * D_HID; p += 256) {
        const int s   = p / D_HID;
        const int row = p - s * D_HID;
        float vals[D_HID];
        if (row == 0) {
            const float o = o2o[s];
            vals[0] = o;
            const float rest = (1.f - o) * (1.f / (float)NM1);
#pragma unroll
            for (int j = 1; j < D_HID; j++) vals[j] = rest;
        } else {
            const int i = row - 1;
            const float x = l2l[s * NM1 + i];
            const float wf = (x < tp) ? ((float)D_OBS * x * x) : x;  // tp*(x/tp)^2 = 17 x^2
            const float omx = 1.f - x;
            vals[0] = omx * (1.f - wf);                   // o_vals
            const float nd = omx * wf * (1.f / 15.f);     // nondiag
#pragma unroll
            for (int j = 0; j < NM1; j++) {
                float base = (i == j) ? x : nd;
                vals[j + 1] = base + wsc[s * NM1 + j] * lut[s * 256 + j * NM1 + i];
            }
        }
        float ssum = 0.f;
#pragma unroll
        for (int t = 0; t < D_HID; t++) {
            float rv = fmaf(vals[t], 99.f, 1.f);          // *(CONC_MAX-CONC_BASE)+CONC_BASE
            vals[t] = rv;
            ssum += rv;
        }
        const float inv = 1.f / ssum;
        float* dst = out + OFF_EMISS + (size_t)b * N_SRC * TRANS_COLS
                         + (size_t)s * TRANS_COLS + (size_t)row * D_HID;
#pragma unroll
        for (int t = 0; t < D_HID; t++) dst[t] = vals[t] * inv;
    }
}

// ---------------------------------------------------------------------------
// launch
// ---------------------------------------------------------------------------
extern "C" void kernel_launch(void* const* d_in, const int* in_sizes, int n_in,
                              void* d_out, int out_size)
{
    const float* embs    = (const float*)d_in[0];
    const float* W_trans = (const float*)d_in[1];
    const float* b_trans = (const float*)d_in[2];
    const float* W_2o    = (const float*)d_in[3];
    const float* b_2o    = (const float*)d_in[4];
    const float* W_2e    = (const float*)d_in[5];
    const float* b_2e    = (const float*)d_in[6];
    const float* W_exp   = (const float*)d_in[7];
    const float* b_exp   = (const float*)d_in[8];
    const float* lut     = (const float*)d_in[9];
    float* out = (float*)d_out;

    // big GEMM: logits -> out[trans region]
    dim3 ggrid((TRANS_COLS + BN - 1) / BN, M_ROWS / BM);   // 5 x 256
    gemm_trans_kernel<<<ggrid, 256>>>(embs, W_trans, b_trans, out + OFF_TRANS);

    // in-place softmax over 17-groups (32768*17 groups / 256 per block = 2176)
    softmax17_kernel<<<(M_ROWS * D_HID) / (256), 256>>>(out + OFF_TRANS);

    // small path
    small_gemv_kernel<<<B_SZ, 256>>>(embs, W_2o, b_2o, W_2e, b_2e, W_exp, b_exp);
    finalize_kernel<<<B_SZ, 256>>>(lut, out);
}

// round 6
// speedup vs baseline: 3.3592x; 3.3592x over previous
#include <cuda_runtime.h>
#include <cuda_bf16.h>
#include <math.h>
#include <stdint.h>

// ---------------------------------------------------------------------------
// Problem constants
// ---------------------------------------------------------------------------
#define B_SZ    64
#define L_SZ    512
#define D_EMB   768
#define D_HID   17
#define D_OBS   17
#define N_SRC   24
#define NM1     16
#define TRANS_COLS (D_HID * D_HID)   // 289
#define M_ROWS  (B_SZ * L_SZ)        // 32768
#define N_PAD   304                  // padded cols for B (rows 289..303 zero)

// output layout (flattened concat of the 5 reference outputs, in order)
#define OFF_TRANS 0ULL
#define SZ_TRANS  ((size_t)M_ROWS * TRANS_COLS)
#define OFF_EMISS (OFF_TRANS + SZ_TRANS)
#define SZ_EMISS  ((size_t)B_SZ * N_SRC * TRANS_COLS)
#define OFF_O2O   (OFF_EMISS + SZ_EMISS)
#define SZ_O2O    ((size_t)B_SZ * N_SRC)
#define OFF_L2L   (OFF_O2O + SZ_O2O)
#define SZ_L2L    ((size_t)B_SZ * N_SRC * NM1)
#define OFF_WXOR  (OFF_L2L + SZ_L2L)
#define SZ_WXOR   ((size_t)B_SZ * N_SRC * NM1 * NM1)

// scratch (device globals; no allocations allowed)
__device__ float g_o2o[B_SZ * N_SRC];
__device__ float g_e2e[B_SZ * N_SRC * NM1];
__device__ float g_exp[B_SZ * N_SRC * NM1];
__device__ __align__(16) __nv_bfloat16 g_Whi[N_PAD * D_EMB];
__device__ __align__(16) __nv_bfloat16 g_Wlo[N_PAD * D_EMB];

// ---------------------------------------------------------------------------
// Helpers (plain sm_100-compatible: mma.sync / ldmatrix / cp.async only)
// ---------------------------------------------------------------------------
__device__ __forceinline__ uint32_t smem_to_u32(const void* p) {
    uint32_t a;
    asm("{ .reg .u64 t; cvta.to.shared.u64 t, %1; cvt.u32.u64 %0, t; }" : "=r"(a) : "l"(p));
    return a;
}
__device__ __forceinline__ void mma16816(float* d, const uint32_t* a, uint32_t b0, uint32_t b1) {
    asm volatile("mma.sync.aligned.m16n8k16.row.col.f32.bf16.bf16.f32 "
        "{%0,%1,%2,%3},{%4,%5,%6,%7},{%8,%9},{%0,%1,%2,%3};"
        : "+f"(d[0]), "+f"(d[1]), "+f"(d[2]), "+f"(d[3])
        : "r"(a[0]), "r"(a[1]), "r"(a[2]), "r"(a[3]), "r"(b0), "r"(b1));
}
__device__ __forceinline__ void ldsm4(uint32_t* r, uint32_t addr) {
    asm volatile("ldmatrix.sync.aligned.m8n8.x4.shared.b16 {%0,%1,%2,%3}, [%4];"
        : "=r"(r[0]), "=r"(r[1]), "=r"(r[2]), "=r"(r[3]) : "r"(addr));
}
__device__ __forceinline__ void ldsm2(uint32_t* r, uint32_t addr) {
    asm volatile("ldmatrix.sync.aligned.m8n8.x2.shared.b16 {%0,%1}, [%2];"
        : "=r"(r[0]), "=r"(r[1]) : "r"(addr));
}
#define CP_ASYNC16(dst, src) \
    asm volatile("cp.async.ca.shared.global [%0], [%1], 16;" :: "r"(dst), "l"(src) : "memory")
#define CP_COMMIT() asm volatile("cp.async.commit_group;" ::: "memory")
#define CP_WAIT(n)  asm volatile("cp.async.wait_group %0;" :: "n"(n) : "memory")

__device__ __forceinline__ void split2(float x, float y, uint32_t& h, uint32_t& l) {
    __nv_bfloat16 hx = __float2bfloat16_rn(x), hy = __float2bfloat16_rn(y);
    float rx = x - __bfloat162float(hx), ry = y - __bfloat162float(hy);
    __nv_bfloat16 lx = __float2bfloat16_rn(rx), ly = __float2bfloat16_rn(ry);
    h = ((uint32_t)__bfloat16_as_ushort(hy) << 16) | __bfloat16_as_ushort(hx);
    l = ((uint32_t)__bfloat16_as_ushort(ly) << 16) | __bfloat16_as_ushort(lx);
}

// ---------------------------------------------------------------------------
// Kernel 0: split W_trans into hi/lo bf16 scratch, zero-pad rows 289..303
// ---------------------------------------------------------------------------
__global__ __launch_bounds__(256) void convert_W_kernel(const float* __restrict__ W)
{
    int idx = blockIdx.x * 256 + threadIdx.x;          // < 304*768
    int row = idx / D_EMB;
    float v = (row < TRANS_COLS) ? W[idx] : 0.f;
    __nv_bfloat16 h = __float2bfloat16_rn(v);
    float r = v - __bfloat162float(h);
    g_Whi[idx] = h;
    g_Wlo[idx] = __float2bfloat16_rn(r);
}

// ---------------------------------------------------------------------------
// Kernel 1: split-bf16 mma.sync GEMM + fused bias + softmax(17-groups)
//   CTA: 128 rows x 304 cols, 512 threads (16 warps: 8M x 2N), K in 24x32.
// ---------------------------------------------------------------------------
#define BK        32
#define NK_ITERS  (D_EMB / BK)            // 24
#define A_PITCH   80                      // bytes per 32-bf16 row (40 bf16)
#define A_BUF_SZ  (128 * A_PITCH)         // 10240
#define B_BUF_SZ  (N_PAD * A_PITCH)       // 24320
#define SM_A      0                       // 4 bufs (b0h,b0l,b1h,b1l): 40960
#define SM_B      40960                   //            + 4x24320 = 97280 -> 138240
#define STAG_PITCH 306
#define SM_BIAS   156672                  // 128*306*4 staging reuses [0,156672)
#define SM_TOTAL  157856

#define A_OFF(buf,hl) (SM_A + ((buf)*2 + (hl)) * A_BUF_SZ)
#define B_OFF(buf,hl) (SM_B + ((buf)*2 + (hl)) * B_BUF_SZ)

__global__ __launch_bounds__(512, 1) void gemm_trans_mma_kernel(
    const float* __restrict__ embs,
    const float* __restrict__ bias,
    float* __restrict__ out)
{
    extern __shared__ char smem[];
    const uint32_t smem_u = smem_to_u32(smem);
    const int tid  = threadIdx.x;
    const int wid  = tid >> 5;
    const int lane = tid & 31;
    const int mw   = wid >> 1;           // 0..7  (M warp: 16 rows each)
    const int nw   = wid & 1;            // 0..1  (N warp: 152 cols each)
    const int m0 = blockIdx.x * 128;

    // bias to smem
    for (int i = tid; i < TRANS_COLS; i += 512)
        *(float*)(smem + SM_BIAS + i * 4) = bias[i];

    // per-lane ldmatrix offsets
    const uint32_t aLaneOff = (uint32_t)((mw * 16 + (lane & 15)) * A_PITCH + (lane >> 4) * 16);
    const uint32_t rowInPair = (lane & 7) + ((lane & 16) >> 1);       // 0..15
    const uint32_t khalf = (lane >> 3) & 1;
    const uint32_t bLaneOff  = (uint32_t)((nw * 152 + rowInPair) * A_PITCH + khalf * 16);
    const uint32_t bLaneOff2 = (uint32_t)((nw * 152 + 144 + (lane & 7)) * A_PITCH + khalf * 16);

    // A global-load mapping: each thread loads 8 fp32 (2 float4) per chunk
    const int arow = tid >> 2;           // 0..127
    const int aq   = tid & 3;            // quarter (8 floats)
    const float* aSrcBase = embs + (size_t)(m0 + arow) * D_EMB + aq * 8;

    float acc[19][4];
#pragma unroll
    for (int j = 0; j < 19; j++)
#pragma unroll
        for (int q = 0; q < 4; q++) acc[j][q] = 0.f;

    // ---- prologue: A regs chunk 0, B cp.async buf0
    float4 aU = ((const float4*)(aSrcBase))[0];
    float4 aV = ((const float4*)(aSrcBase))[1];
    {
        const int k0 = 0;
        for (int c = tid; c < 2432; c += 512) {
            const int hl = (c >= 1216);
            const int r = (c - hl * 1216) >> 2;
            const int seg = c & 3;
            const __nv_bfloat16* src = (hl ? g_Wlo : g_Whi) + (size_t)r * D_EMB + k0 + seg * 8;
            CP_ASYNC16(smem_u + B_OFF(0, hl) + r * A_PITCH + seg * 16, src);
        }
        CP_COMMIT();
    }

    for (int it = 0; it < NK_ITERS; it++) {
        const int buf = it & 1;
        // issue next B tile (into buf^1 — safe: previous iteration ended with
        // a trailing __syncthreads, so no warp is still reading buf^1)
        if (it < NK_ITERS - 1) {
            const int k0 = (it + 1) * BK;
            for (int c = tid; c < 2432; c += 512) {
                const int hl = (c >= 1216);
                const int r = (c - hl * 1216) >> 2;
                const int seg = c & 3;
                const __nv_bfloat16* src = (hl ? g_Wlo : g_Whi) + (size_t)r * D_EMB + k0 + seg * 8;
                CP_ASYNC16(smem_u + B_OFF(buf ^ 1, hl) + r * A_PITCH + seg * 16, src);
            }
            CP_COMMIT();
        }
        // convert current A regs -> smem(buf)
        {
            uint32_t hi[4], lo[4];
            split2(aU.x, aU.y, hi[0], lo[0]);
            split2(aU.z, aU.w, hi[1], lo[1]);
            split2(aV.x, aV.y, hi[2], lo[2]);
            split2(aV.z, aV.w, hi[3], lo[3]);
            const uint32_t d = arow * A_PITCH + aq * 16;
            *(uint4*)(smem + A_OFF(buf, 0) + d) = make_uint4(hi[0], hi[1], hi[2], hi[3]);
            *(uint4*)(smem + A_OFF(buf, 1) + d) = make_uint4(lo[0], lo[1], lo[2], lo[3]);
        }
        // prefetch A regs for next chunk
        if (it < NK_ITERS - 1) {
            const float* s = aSrcBase + (it + 1) * BK;
            aU = ((const float4*)s)[0];
            aV = ((const float4*)s)[1];
        }
        if (it < NK_ITERS - 1) { CP_WAIT(1); } else { CP_WAIT(0); }
        __syncthreads();   // B(buf) landed, A(buf) converted, all warps aligned

        // ---- compute on buf
        const uint32_t aHi = smem_u + A_OFF(buf, 0) + aLaneOff;
        const uint32_t aLo = smem_u + A_OFF(buf, 1) + aLaneOff;
        const uint32_t bHi = smem_u + B_OFF(buf, 0) + bLaneOff;
        const uint32_t bLo = smem_u + B_OFF(buf, 1) + bLaneOff;
        const uint32_t bHi2 = smem_u + B_OFF(buf, 0) + bLaneOff2;
        const uint32_t bLo2 = smem_u + B_OFF(buf, 1) + bLaneOff2;
#pragma unroll
        for (int s = 0; s < 2; s++) {
            const uint32_t so = s * 32;  // k-step byte offset (16 bf16)
            uint32_t ah[4], al[4];
            ldsm4(ah, aHi + so);
            ldsm4(al, aLo + so);
#pragma unroll
            for (int jp = 0; jp < 9; jp++) {
                const uint32_t off = jp * (16 * A_PITCH);
                uint32_t bh[4], bl[4];
                ldsm4(bh, bHi + off + so);
                ldsm4(bl, bLo + off + so);
                mma16816(acc[2*jp],   ah, bh[0], bh[1]);
                mma16816(acc[2*jp+1], ah, bh[2], bh[3]);
                mma16816(acc[2*jp],   ah, bl[0], bl[1]);
                mma16816(acc[2*jp+1], ah, bl[2], bl[3]);
                mma16816(acc[2*jp],   al, bh[0], bh[1]);
                mma16816(acc[2*jp+1], al, bh[2], bh[3]);
            }
            {   // j = 18 (last single n8 tile)
                uint32_t bh[2], bl[2];
                ldsm2(bh, bHi2 + so);
                ldsm2(bl, bLo2 + so);
                mma16816(acc[18], ah, bh[0], bh[1]);
                mma16816(acc[18], ah, bl[0], bl[1]);
                mma16816(acc[18], al, bh[0], bh[1]);
            }
        }
        // REQUIRED: no warp may proceed to overwrite buf^1 (next iteration's
        // prefetch target == this iteration's... the other buffer read by
        // laggards) until every warp finished consuming smem this iteration.
        __syncthreads();
    }

    // ---- epilogue: accumulators -> staging smem (smem reuse is safe: the
    // loop ended with __syncthreads, all compute done)
    float* stag = (float*)smem;
    {
        const int r0 = mw * 16 + (lane >> 2);
        const int nbase = nw * 152 + (lane & 3) * 2;
#pragma unroll
        for (int j = 0; j < 19; j++) {
            const int n = nbase + j * 8;
            if (n < 288) {
                stag[r0 * STAG_PITCH + n]           = acc[j][0];
                stag[r0 * STAG_PITCH + n + 1]       = acc[j][1];
                stag[(r0 + 8) * STAG_PITCH + n]     = acc[j][2];
                stag[(r0 + 8) * STAG_PITCH + n + 1] = acc[j][3];
            } else if (n == 288) {
                stag[r0 * STAG_PITCH + 288]       = acc[j][0];
                stag[(r0 + 8) * STAG_PITCH + 288] = acc[j][2];
            }
        }
    }
    __syncthreads();

    // ---- bias + softmax over contiguous 17-groups
    const float* biasS = (const float*)(smem + SM_BIAS);
    for (int t = tid; t < 128 * D_HID; t += 512) {
        const int row = t / D_HID;
        const int g = t - row * D_HID;
        float* p = stag + row * STAG_PITCH + g * D_HID;
        const float* bb = biasS + g * D_HID;
        float v[D_HID];
        float mx = -1e30f;
#pragma unroll
        for (int j = 0; j < D_HID; j++) { v[j] = p[j] + bb[j]; mx = fmaxf(mx, v[j]); }
        float s = 0.f;
#pragma unroll
        for (int j = 0; j < D_HID; j++) { float e = __expf(v[j] - mx); v[j] = e; s += e; }
        const float inv = 1.f / s;
#pragma unroll
        for (int j = 0; j < D_HID; j++) p[j] = v[j] * inv;
    }
    __syncthreads();

    // ---- coalesced contiguous store
    float* obase = out + (size_t)blockIdx.x * (128 * TRANS_COLS);
    for (int idx = tid; idx < 128 * TRANS_COLS; idx += 512) {
        const int r = idx / TRANS_COLS;
        const int c = idx - r * TRANS_COLS;
        obase[idx] = stag[r * STAG_PITCH + c];
    }
}

// ---------------------------------------------------------------------------
// Kernel 2: tiny GEMVs off x0 = embs[b,0,:]; grid (64, 12)
// ---------------------------------------------------------------------------
__global__ __launch_bounds__(256) void small_gemv_kernel(
    const float* __restrict__ embs,
    const float* __restrict__ W2o, const float* __restrict__ b2o,
    const float* __restrict__ W2e, const float* __restrict__ b2e,
    const float* __restrict__ Wexp, const float* __restrict__ bexp)
{
    __shared__ float x0[D_EMB];
    const int b = blockIdx.x;
    const int seg = blockIdx.y;              // 0..11, 66 cols each (792 total)
    const float* xrow = embs + (size_t)b * L_SZ * D_EMB;
    for (int i = threadIdx.x; i < D_EMB; i += 256) x0[i] = xrow[i];
    __syncthreads();

    const int warp = threadIdx.x >> 5;
    const int lane = threadIdx.x & 31;
    const int cend = (seg + 1) * 66;

    for (int col = seg * 66 + warp; col < cend; col += 8) {
        const float* w; float bv; float* dst;
        if (col < 24) {
            w = W2o + (size_t)col * D_EMB;  bv = b2o[col];
            dst = &g_o2o[b * N_SRC + col];
        } else if (col < 24 + N_SRC * NM1) {
            int c = col - 24;
            w = W2e + (size_t)c * D_EMB;    bv = b2e[c];
            dst = &g_e2e[b * N_SRC * NM1 + c];
        } else {
            int c = col - 24 - N_SRC * NM1;
            w = Wexp + (size_t)c * D_EMB;   bv = bexp[c];
            dst = &g_exp[b * N_SRC * NM1 + c];
        }
        float s = 0.f;
        for (int k = lane; k < D_EMB; k += 32) s = fmaf(x0[k], w[k], s);
#pragma unroll
        for (int o = 16; o > 0; o >>= 1) s += __shfl_xor_sync(0xffffffffu, s, o);
        if (lane == 0) *dst = s + bv;
    }
}

// ---------------------------------------------------------------------------
// Kernel 3: finalize (512 threads; warp-shuffle softmax over sources)
// ---------------------------------------------------------------------------
__device__ __forceinline__ float sigmoidf_(float x) { return 1.f / (1.f + __expf(-x)); }

__global__ __launch_bounds__(512) void finalize_kernel(
    const float* __restrict__ lut, float* __restrict__ out)
{
    __shared__ float l2l[N_SRC * NM1];
    __shared__ float wsc[N_SRC * NM1];
    __shared__ float o2o[N_SRC];

    const int b = blockIdx.x;
    const int tid = threadIdx.x;
    const int warp = tid >> 5, lane = tid & 31;

    if (tid < N_SRC * NM1) {
        l2l[tid] = g_e2e[b * N_SRC * NM1 + tid];
        wsc[tid] = sigmoidf_(g_exp[b * N_SRC * NM1 + tid]);
    }
    if (tid < N_SRC) o2o[tid] = sigmoidf_(g_o2o[b * N_SRC + tid]);
    __syncthreads();

    // warp j handles column j (16 warps): softmax over 24 sources + prob_scaling
    {
        const int j = warp;                    // 0..15
        float x = (lane < N_SRC) ? l2l[lane * NM1 + j] : -1e30f;
        float mx = x;
#pragma unroll
        for (int o = 16; o > 0; o >>= 1) mx = fmaxf(mx, __shfl_xor_sync(0xffffffffu, mx, o));
        float e = (lane < N_SRC) ? __expf(x - mx) : 0.f;
        float s = e;
#pragma unroll
        for (int o = 16; o > 0; o >>= 1) s += __shfl_xor_sync(0xffffffffu, s, o);
        if (lane < N_SRC) {
            const float xn = e / s;
            const float r = 1.f / 24.f;
            const float omr = 1.f - r;
            const float bco = 1.f / (omr * omr * omr);
            float om = 1.f - xn;
            float om2 = om * om;
            l2l[lane * NM1 + j] = (xn < r) ? xn : (1.f - bco * om2 * om2);
        }
    }
    __syncthreads();

    if (tid < N_SRC) out[OFF_O2O + (size_t)b * N_SRC + tid] = o2o[tid];
    if (tid < N_SRC * NM1)
        out[OFF_L2L + (size_t)b * N_SRC * NM1 + tid] = l2l[tid];

    // scaled_wxor[b,s,i,j] = wsc[s,j] * lut[s,j,i]
    if (tid < N_SRC * NM1) {
        const int s = tid >> 4;
        const int i = tid & 15;
        float* dst = out + OFF_WXOR + (size_t)b * (N_SRC * NM1 * NM1) + (size_t)tid * NM1;
#pragma unroll
        for (int j = 0; j < NM1; j++)
            dst[j] = wsc[s * NM1 + j] * lut[s * 256 + j * NM1 + i];
    }

    // emission probs: 24 sources x 17 rows
    const float tp = 1.f / (float)D_OBS;
    if (tid < N_SRC * D_HID) {
        const int s   = tid / D_HID;
        const int row = tid - s * D_HID;
        float vals[D_HID];
        if (row == 0) {
            const float o = o2o[s];
            vals[0] = o;
            const float rest = (1.f - o) * (1.f / (float)NM1);
#pragma unroll
            for (int j = 1; j < D_HID; j++) vals[j] = rest;
        } else {
            const int i = row - 1;
            const float x = l2l[s * NM1 + i];
            const float wf = (x < tp) ? ((float)D_OBS * x * x) : x;
            const float omx = 1.f - x;
            vals[0] = omx * (1.f - wf);
            const float nd = omx * wf * (1.f / 15.f);
#pragma unroll
            for (int j = 0; j < NM1; j++) {
                float base = (i == j) ? x : nd;
                vals[j + 1] = base + wsc[s * NM1 + j] * lut[s * 256 + j * NM1 + i];
            }
        }
        float ssum = 0.f;
#pragma unroll
        for (int t = 0; t < D_HID; t++) {
            float rv = fmaf(vals[t], 99.f, 1.f);
            vals[t] = rv;
            ssum += rv;
        }
        const float inv = 1.f / ssum;
        float* dst = out + OFF_EMISS + (size_t)b * N_SRC * TRANS_COLS
                         + (size_t)s * TRANS_COLS + (size_t)row * D_HID;
#pragma unroll
        for (int t = 0; t < D_HID; t++) dst[t] = vals[t] * inv;
    }
}

// ---------------------------------------------------------------------------
// launch
// ---------------------------------------------------------------------------
extern "C" void kernel_launch(void* const* d_in, const int* in_sizes, int n_in,
                              void* d_out, int out_size)
{
    const float* embs    = (const float*)d_in[0];
    const float* W_trans = (const float*)d_in[1];
    const float* b_trans = (const float*)d_in[2];
    const float* W_2o    = (const float*)d_in[3];
    const float* b_2o    = (const float*)d_in[4];
    const float* W_2e    = (const float*)d_in[5];
    const float* b_2e    = (const float*)d_in[6];
    const float* W_exp   = (const float*)d_in[7];
    const float* b_exp   = (const float*)d_in[8];
    const float* lut     = (const float*)d_in[9];
    float* out = (float*)d_out;

    cudaFuncSetAttribute(gemm_trans_mma_kernel,
                         cudaFuncAttributeMaxDynamicSharedMemorySize, SM_TOTAL);

    // split W into hi/lo bf16 (304x768, zero-padded)
    convert_W_kernel<<<(N_PAD * D_EMB) / 256, 256>>>(W_trans);

    // tensor-core (mma.sync) GEMM + fused bias + softmax
    gemm_trans_mma_kernel<<<M_ROWS / 128, 512, SM_TOTAL>>>(embs, b_trans, out + OFF_TRANS);

    // small path
    small_gemv_kernel<<<dim3(B_SZ, 12), 256>>>(embs, W_2o, b_2o, W_2e, b_2e, W_exp, b_exp);
    finalize_kernel<<<B_SZ, 512>>>(lut, out);
}